// round 4
// baseline (speedup 1.0000x reference)
#include <cuda_runtime.h>

#define H 512
#define W 512
#define NB 32
#define WG8 (W / 8)   // 64 groups of 8 pixels per row

// One thread = 8 contiguous pixels of one row (two float4 loads/row).
// A warp covers 256 px = half a row. Horizontal halo via warp shuffle;
// strip-edge lanes fetch the true neighbor scalar.
__global__ __launch_bounds__(256) void sqdiff_mag_kernel(
    const float* __restrict__ x, float* __restrict__ out)
{
    int idx  = blockIdx.x * blockDim.x + threadIdx.x;
    int lane = threadIdx.x & 31;

    int wg = idx & (WG8 - 1);       // 8-px group in row
    int t  = idx >> 6;
    int h  = t & (H - 1);
    int n  = t >> 9;

    int w     = wg * 8;
    int wbase = w & ~255;           // warp strip start (0 or 256)

    const size_t plane = (size_t)H * W;
    const float* g = x + ((size_t)n * 3 + 1) * plane;  // channel 1

    // r[j][0] = left halo, r[j][1..8] = pixels, r[j][9] = right halo
    float r[3][10];

    #define LOAD_ROW(j, hh)                                                    \
    {                                                                          \
        const float* p = g + (size_t)(hh) * W + w;                             \
        float4 v0 = *reinterpret_cast<const float4*>(p);                       \
        float4 v1 = *reinterpret_cast<const float4*>(p + 4);                   \
        r[j][1] = v0.x; r[j][2] = v0.y; r[j][3] = v0.z; r[j][4] = v0.w;        \
        r[j][5] = v1.x; r[j][6] = v1.y; r[j][7] = v1.z; r[j][8] = v1.w;        \
        float lft = __shfl_up_sync(0xffffffffu, v1.w, 1);                      \
        float rgt = __shfl_down_sync(0xffffffffu, v0.x, 1);                    \
        if (lane == 0)  lft = (wbase > 0)       ? __ldg(p - 1) : 0.0f;         \
        if (lane == 31) rgt = (wbase + 256 < W) ? __ldg(p + 8) : 0.0f;         \
        r[j][0] = lft; r[j][9] = rgt;                                          \
    }

    LOAD_ROW(1, h)
    if (h > 0) {
        LOAD_ROW(0, h - 1)
    } else {
        #pragma unroll
        for (int i = 0; i < 10; i++) r[0][i] = 0.0f;
    }
    if (h + 1 < H) {
        LOAD_ROW(2, h + 1)
    } else {
        #pragma unroll
        for (int i = 0; i < 10; i++) r[2][i] = 0.0f;
    }
    #undef LOAD_ROW

    float4 resA, resB;
    float* ra = reinterpret_cast<float*>(&resA);
    float* rb = reinterpret_cast<float*>(&resB);

    #pragma unroll
    for (int i = 0; i < 8; i++) {
        float c  = r[1][i + 1];
        float d0 = c - r[1][i + 2];
        float d1 = c - r[1][i];
        float d2 = c - r[2][i + 1];
        float d3 = c - r[0][i + 1];
        float d4 = c - r[2][i + 2];
        float d5 = c - r[2][i];
        float d6 = c - r[0][i + 2];
        float d7 = c - r[0][i];
        float s = d0 * d0;
        s = fmaf(d1, d1, s);
        s = fmaf(d2, d2, s);
        s = fmaf(d3, d3, s);
        s = fmaf(d4, d4, s);
        s = fmaf(d5, d5, s);
        s = fmaf(d6, d6, s);
        s = fmaf(d7, d7, s);
        float m = sqrtf(s);
        if (i < 4) ra[i] = m; else rb[i - 4] = m;
    }

    float* ob = out + (size_t)n * 3 * plane + (size_t)h * W + w;
    __stcs(reinterpret_cast<float4*>(ob),                 resA);
    __stcs(reinterpret_cast<float4*>(ob + 4),             resB);
    __stcs(reinterpret_cast<float4*>(ob + plane),         resA);
    __stcs(reinterpret_cast<float4*>(ob + plane + 4),     resB);
    __stcs(reinterpret_cast<float4*>(ob + 2 * plane),     resA);
    __stcs(reinterpret_cast<float4*>(ob + 2 * plane + 4), resB);
}

extern "C" void kernel_launch(void* const* d_in, const int* in_sizes, int n_in,
                              void* d_out, int out_size)
{
    const float* x = (const float*)d_in[0];
    float* out = (float*)d_out;

    int total_threads = NB * H * WG8;   // 32*512*64 = 1,048,576
    int block = 256;
    int grid = total_threads / block;   // 4096
    sqdiff_mag_kernel<<<grid, block>>>(x, out);
}

// round 5
// speedup vs baseline: 1.3019x; 1.3019x over previous
#include <cuda_runtime.h>
#include <cstdint>

#define H 512
#define W 512
#define NB 32

// Packed f32x2 helpers (sm_103a): one instruction = two fp32 lanes.
#define PACK2(d, lo, hi) \
    asm("mov.b64 %0, {%1, %2};" : "=l"(d) : "r"(__float_as_uint(lo)), "r"(__float_as_uint(hi)))
#define UNPACK2(lo, hi, s) \
    asm("mov.b64 {%0, %1}, %2;" : "=r"(lo), "=r"(hi) : "l"(s))
#define SUB2(d, a, b) \
    asm("sub.rn.f32x2 %0, %1, %2;" : "=l"(d) : "l"(a), "l"(b))
#define MUL2(d, a, b) \
    asm("mul.rn.f32x2 %0, %1, %2;" : "=l"(d) : "l"(a), "l"(b))
#define FMA2(d, a, b, c) \
    asm("fma.rn.f32x2 %0, %1, %2, %3;" : "=l"(d) : "l"(a), "l"(b), "l"(c))
#define SQRT_APPROX(d, a) \
    asm("sqrt.approx.f32 %0, %1;" : "=f"(d) : "f"(a))

// R3 memory shape: 1 thread = 4 contiguous px of one row (float4 coalesced),
// halo via warp shuffle; compute in packed f32x2 pairs.
__global__ __launch_bounds__(256) void sqdiff_mag_kernel(
    const float* __restrict__ x, float* __restrict__ out)
{
    int idx  = blockIdx.x * 256 + threadIdx.x;
    int lane = threadIdx.x & 31;

    int wg = idx & 127;          // float4 group in row
    int t  = idx >> 7;
    int h  = t & (H - 1);
    int n  = t >> 9;

    int w     = wg << 2;
    int wbase = w & ~127;        // warp's 128-px strip start

    const size_t plane = (size_t)H * W;
    const float* g = x + ((size_t)n * 3 + 1) * plane;   // channel 1

    // Per row j: pixels c1..c4 (float4) + halo c0,c5 packed as f32x2 pairs:
    //   A=(c1,c2)  B=(c3,c4)  L=(c0,c1)  M=(c2,c3)  R=(c4,c5)
    unsigned long long A[3], Bp[3], L[3], M[3], R[3];

    #define LOAD_ROW(j, hh)                                                    \
    {                                                                          \
        const float* p = g + (size_t)(hh) * W + w;                             \
        float4 v = *reinterpret_cast<const float4*>(p);                        \
        float lft = __shfl_up_sync(0xffffffffu, v.w, 1);                       \
        float rgt = __shfl_down_sync(0xffffffffu, v.x, 1);                     \
        if (lane == 0)  lft = (wbase > 0)       ? __ldg(p - 1) : 0.0f;         \
        if (lane == 31) rgt = (wbase + 128 < W) ? __ldg(p + 4) : 0.0f;         \
        PACK2(A[j],  v.x, v.y);                                                \
        PACK2(Bp[j], v.z, v.w);                                                \
        PACK2(L[j],  lft, v.x);                                                \
        PACK2(M[j],  v.y, v.z);                                                \
        PACK2(R[j],  v.w, rgt);                                                \
    }

    LOAD_ROW(1, h)
    if (h > 0) {
        LOAD_ROW(0, h - 1)
    } else {
        A[0] = Bp[0] = L[0] = M[0] = R[0] = 0ull;
    }
    if (h + 1 < H) {
        LOAD_ROW(2, h + 1)
    } else {
        A[2] = Bp[2] = L[2] = M[2] = R[2] = 0ull;
    }
    #undef LOAD_ROW

    unsigned long long C1 = A[1];   // centers (px0,px1)
    unsigned long long C2 = Bp[1];  // centers (px2,px3)
    unsigned long long d, s1, s2;

    // pair1: neighbors up: L0,A0,M0 ; mid: L1,M1 ; down: L2,A2,M2
    SUB2(d, C1, L[0]);   MUL2(s1, d, d);
    SUB2(d, C1, A[0]);   FMA2(s1, d, d, s1);
    SUB2(d, C1, M[0]);   FMA2(s1, d, d, s1);
    SUB2(d, C1, L[1]);   FMA2(s1, d, d, s1);
    SUB2(d, C1, M[1]);   FMA2(s1, d, d, s1);
    SUB2(d, C1, L[2]);   FMA2(s1, d, d, s1);
    SUB2(d, C1, A[2]);   FMA2(s1, d, d, s1);
    SUB2(d, C1, M[2]);   FMA2(s1, d, d, s1);

    // pair2: neighbors up: M0,B0,R0 ; mid: M1,R1 ; down: M2,B2,R2
    SUB2(d, C2, M[0]);   MUL2(s2, d, d);
    SUB2(d, C2, Bp[0]);  FMA2(s2, d, d, s2);
    SUB2(d, C2, R[0]);   FMA2(s2, d, d, s2);
    SUB2(d, C2, M[1]);   FMA2(s2, d, d, s2);
    SUB2(d, C2, R[1]);   FMA2(s2, d, d, s2);
    SUB2(d, C2, M[2]);   FMA2(s2, d, d, s2);
    SUB2(d, C2, Bp[2]);  FMA2(s2, d, d, s2);
    SUB2(d, C2, R[2]);   FMA2(s2, d, d, s2);

    uint32_t u0, u1, u2, u3;
    UNPACK2(u0, u1, s1);
    UNPACK2(u2, u3, s2);

    float4 res;
    SQRT_APPROX(res.x, __uint_as_float(u0));
    SQRT_APPROX(res.y, __uint_as_float(u1));
    SQRT_APPROX(res.z, __uint_as_float(u2));
    SQRT_APPROX(res.w, __uint_as_float(u3));

    float* ob = out + (size_t)n * 3 * plane + (size_t)h * W + w;
    __stcs(reinterpret_cast<float4*>(ob),             res);
    __stcs(reinterpret_cast<float4*>(ob + plane),     res);
    __stcs(reinterpret_cast<float4*>(ob + 2 * plane), res);
}

extern "C" void kernel_launch(void* const* d_in, const int* in_sizes, int n_in,
                              void* d_out, int out_size)
{
    const float* x = (const float*)d_in[0];
    float* out = (float*)d_out;

    int total_threads = NB * H * (W / 4);   // 2,097,152 (exact)
    sqdiff_mag_kernel<<<total_threads / 256, 256>>>(x, out);
}

// round 6
// speedup vs baseline: 1.5144x; 1.1632x over previous
#include <cuda_runtime.h>

#define H 512
#define W 512
#define NB 32

#define SQRT_APPROX(d, a) \
    asm("sqrt.approx.f32 %0, %1;" : "=f"(d) : "f"(a))

// R3 shape: 1 thread = 4 contiguous px of one row (coalesced float4),
// horizontal halo via warp shuffle. Changes vs R3: approx sqrt (MUFU)
// instead of IEEE sqrt expansion, and 3D-grid index math.
// Block = 256 threads = 2 rows. Grid = (H/2, NB).
__global__ __launch_bounds__(256) void sqdiff_mag_kernel(
    const float* __restrict__ x, float* __restrict__ out)
{
    int lane = threadIdx.x & 31;
    int wg   = threadIdx.x & 127;                     // float4 group in row
    int h    = (blockIdx.x << 1) + (threadIdx.x >> 7);
    int n    = blockIdx.y;

    int w     = wg << 2;
    int wbase = w & ~127;                             // warp's 128-px strip

    const size_t plane = (size_t)H * W;
    const float* g = x + ((size_t)n * 3 + 1) * plane; // channel 1

    float rm[6], rc[6], rp[6];

    #define LOAD_ROW(dst, hh)                                                  \
    {                                                                          \
        const float* p = g + (size_t)(hh) * W + w;                             \
        float4 v = *reinterpret_cast<const float4*>(p);                        \
        dst[1] = v.x; dst[2] = v.y; dst[3] = v.z; dst[4] = v.w;                \
        float lft = __shfl_up_sync(0xffffffffu, v.w, 1);                       \
        float rgt = __shfl_down_sync(0xffffffffu, v.x, 1);                     \
        if (lane == 0)  lft = (wbase > 0)       ? __ldg(p - 1) : 0.0f;         \
        if (lane == 31) rgt = (wbase + 128 < W) ? __ldg(p + 4) : 0.0f;         \
        dst[0] = lft; dst[5] = rgt;                                            \
    }

    LOAD_ROW(rc, h)
    if (h > 0) {
        LOAD_ROW(rm, h - 1)
    } else {
        #pragma unroll
        for (int i = 0; i < 6; i++) rm[i] = 0.0f;
    }
    if (h + 1 < H) {
        LOAD_ROW(rp, h + 1)
    } else {
        #pragma unroll
        for (int i = 0; i < 6; i++) rp[i] = 0.0f;
    }
    #undef LOAD_ROW

    float4 res;
    float* resp = reinterpret_cast<float*>(&res);

    #pragma unroll
    for (int i = 0; i < 4; i++) {
        float c  = rc[i + 1];
        float d0 = c - rc[i + 2];
        float d1 = c - rc[i];
        float d2 = c - rp[i + 1];
        float d3 = c - rm[i + 1];
        float d4 = c - rp[i + 2];
        float d5 = c - rp[i];
        float d6 = c - rm[i + 2];
        float d7 = c - rm[i];
        float s = d0 * d0;
        s = fmaf(d1, d1, s);
        s = fmaf(d2, d2, s);
        s = fmaf(d3, d3, s);
        s = fmaf(d4, d4, s);
        s = fmaf(d5, d5, s);
        s = fmaf(d6, d6, s);
        s = fmaf(d7, d7, s);
        SQRT_APPROX(resp[i], s);
    }

    float* ob = out + (size_t)n * 3 * plane + (size_t)h * W + w;
    __stcs(reinterpret_cast<float4*>(ob),             res);
    __stcs(reinterpret_cast<float4*>(ob + plane),     res);
    __stcs(reinterpret_cast<float4*>(ob + 2 * plane), res);
}

extern "C" void kernel_launch(void* const* d_in, const int* in_sizes, int n_in,
                              void* d_out, int out_size)
{
    const float* x = (const float*)d_in[0];
    float* out = (float*)d_out;

    dim3 grid(H / 2, NB);     // 256 x 32 blocks
    sqdiff_mag_kernel<<<grid, 256>>>(x, out);
}